// round 10
// baseline (speedup 1.0000x reference)
#include <cuda_runtime.h>

#define HH 768
#define WW 768
#define CC 64
#define NSEG 385
#define NTHREADS 64
#define PER_T (HH / NTHREADS)     // 12 mask elems per scan thread
#define GRID_BLOCKS 4736          // 148 SM x 32 CTA slots
#define NWARPS_TOTAL (GRID_BLOCKS * 2)

// ---------------------------------------------------------------------------
// Fused grid pooling, HALF-WARP-per-cell:
//   prolog: every block redundantly scans both masks into SMEM segment tables.
//   main:   each 16-lane half-warp owns one cell (lane = channel quad).
//           A half-warp access = 1 whole pixel = 256B contiguous.
//           NO cross-lane reduce: each lane sums its own quad over the whole
//           rectangle -> mean is a per-lane multiply. 2 cells in flight per
//           warp, zero barriers, zero shuffles in the main loop.
//   Traffic floor: 151MB read + 151MB write.
// ---------------------------------------------------------------------------
__global__ void __launch_bounds__(NTHREADS, 28)
fused_grid_pool(const float* __restrict__ in,
                const int* __restrict__ h_mask,
                const int* __restrict__ v_mask,
                float* __restrict__ out) {
    __shared__ int s_row_start[NSEG + 1];
    __shared__ int s_col_start[NSEG + 1];
    __shared__ int s_tmp[2];
    __shared__ int s_nrow, s_ncol;

    const int t = threadIdx.x;
    const int lane = t & 31, w = t >> 5;

    // ---- prolog: build segment starts for both masks ----
    #pragma unroll
    for (int axis = 0; axis < 2; ++axis) {
        const int* m = (axis == 0) ? h_mask : v_mask;
        int* start   = (axis == 0) ? s_row_start : s_col_start;

        const int base = t * PER_T;
        int pm = (base == 0) ? 1 : m[base - 1];   // pm=1 at i=0 forces rise[0]=0
        int rises = 0, cnt = 0;
        #pragma unroll
        for (int k = 0; k < PER_T; ++k) {
            const int mv = m[base + k];
            const int r = (mv == 1 && pm == 0);
            rises |= (r << k);
            cnt += r;
            pm = mv;
        }
        int v = cnt;
        #pragma unroll
        for (int o = 1; o < 32; o <<= 1) {
            int n = __shfl_up_sync(0xFFFFFFFFu, v, o);
            if (lane >= o) v += n;
        }
        if (lane == 31) s_tmp[w] = v;
        __syncthreads();
        const int add   = (w == 1) ? s_tmp[0] : 0;
        const int total = s_tmp[0] + s_tmp[1];
        const int excl  = v + add - cnt;

        int sid = excl;
        #pragma unroll
        for (int k = 0; k < PER_T; ++k) {
            if ((rises >> k) & 1) { ++sid; start[sid] = base + k; }
        }
        const int nseg = total + 1;
        if (t == 0) {
            start[0] = 0; start[nseg] = HH;
            if (axis == 0) s_nrow = nseg; else s_ncol = nseg;
        }
        __syncthreads();
    }

    const int nrow = s_nrow, ncol = s_ncol;
    const int total_cells = nrow * ncol;

    const int cg   = lane & 15;   // channel quad within half-warp
    const int half = lane >> 4;   // which cell of the pair this lane serves
    const int gw   = blockIdx.x * 2 + w;   // global warp id

    // ---- main: each half-warp owns one cell; warp strides over PAIRS ----
    for (int pair = gw; pair * 2 < total_cells; pair += NWARPS_TOTAL) {
        const int cell = pair * 2 + half;
        int rs = 0, re = 0, cs = 0, ce = 0;
        if (cell < total_cells) {
            const int rseg = cell / ncol;
            const int cseg = cell - rseg * ncol;
            cs = s_col_start[cseg]; ce = s_col_start[cseg + 1];
            rs = s_row_start[rseg]; re = s_row_start[rseg + 1];
        }

        float4 a0 = make_float4(0.f, 0.f, 0.f, 0.f);
        float4 a1 = make_float4(0.f, 0.f, 0.f, 0.f);

        int y = rs;
        for (; y + 1 < re; y += 2) {
            const float4* r0 = reinterpret_cast<const float4*>(
                in + (size_t)y * WW * CC);
            const float4* r1 = r0 + WW * (CC / 4);
            #pragma unroll 4
            for (int x = cs; x < ce; ++x) {
                const float4 v0 = __ldg(&r0[x * 16 + cg]);
                const float4 v1 = __ldg(&r1[x * 16 + cg]);
                a0.x += v0.x; a0.y += v0.y; a0.z += v0.z; a0.w += v0.w;
                a1.x += v1.x; a1.y += v1.y; a1.z += v1.z; a1.w += v1.w;
            }
        }
        if (y < re) {
            const float4* r0 = reinterpret_cast<const float4*>(
                in + (size_t)y * WW * CC);
            #pragma unroll 4
            for (int x = cs; x < ce; ++x) {
                const float4 v0 = __ldg(&r0[x * 16 + cg]);
                a0.x += v0.x; a0.y += v0.y; a0.z += v0.z; a0.w += v0.w;
            }
        }

        const float inv = (re > rs && ce > cs)
                        ? 1.0f / (float)((re - rs) * (ce - cs)) : 0.f;
        float4 mv;
        mv.x = (a0.x + a1.x) * inv;
        mv.y = (a0.y + a1.y) * inv;
        mv.z = (a0.z + a1.z) * inv;
        mv.w = (a0.w + a1.w) * inv;

        // broadcast: half-warp writes its cell, 256B per (y,x) pixel
        for (int y2 = rs; y2 < re; ++y2) {
            float4* ro = reinterpret_cast<float4*>(out + (size_t)y2 * WW * CC);
            #pragma unroll 4
            for (int x = cs; x < ce; ++x)
                ro[x * 16 + cg] = mv;
        }
    }
}

// ---------------------------------------------------------------------------
extern "C" void kernel_launch(void* const* d_in, const int* in_sizes, int n_in,
                              void* d_out, int out_size) {
    const float* in = (const float*)d_in[0];
    const int*   hm = (const int*)d_in[1];
    const int*   vm = (const int*)d_in[2];
    float*       out = (float*)d_out;

    fused_grid_pool<<<GRID_BLOCKS, NTHREADS>>>(in, hm, vm, out);
}